// round 7
// baseline (speedup 1.0000x reference)
#include <cuda_runtime.h>
#include <cstdint>

// DirectionalStateScan2D: B=8, C=256, H=128, W=128, fp32.
// Persistent CTAs, double-buffered cp.async plane prefetch, NT=1024
// (32 warps -> 50% occupancy; register-restructured to fit 64 regs/thread).
//
// Swizzle: phys(r,w) = r*128 + 4*((w>>2 ^ r>>2)&31) + (w&3).
//  - row float4 access conflict-free; vertical 4x4-block float4 access
//    conflict-free ((G ^ lane) mod 8 distinct per 8-lane phase).

#define Hh 128
#define Ww 128
#define Cc 256
#define PLANE (Hh * Ww)
#define NPLANES (8 * Cc)
#define NT 1024
#define NW (NT / 32)          // 32 warps
#define FULL 0xFFFFFFFFu

struct DirP {
    float d1, d2, d3, d4;   // d^1..d^4
    float q1, q2, q3, q4;   // d^8, d^16, d^32, d^64
    float c;                // (1-d)*scale
};

__device__ __forceinline__ DirP make_dir(const float* __restrict__ decay_logits,
                                         const float* __restrict__ input_scale,
                                         int dir, int ch)
{
    float d = 1.0f / (1.0f + expf(-decay_logits[dir * Cc + ch]));
    d = fminf(fmaxf(d, 0.05f), 0.995f);
    float sc = 1.0f + tanhf(input_scale[dir * Cc + ch]);
    DirP P;
    P.d1 = d;
    P.d2 = d * d;
    P.d3 = P.d2 * d;
    P.d4 = P.d2 * P.d2;
    P.q1 = P.d4 * P.d4;
    P.q2 = P.q1 * P.q1;
    P.q3 = P.q2 * P.q2;
    P.q4 = P.q3 * P.q3;
    P.c  = (1.0f - d) * sc;
    return P;
}

__device__ __forceinline__ void scan_fwd(const DirP& P, int lane,
        float x0, float x1, float x2, float x3,
        float& s0, float& s1, float& s2, float& s3)
{
    float l0 = P.c * x0;
    float l1 = fmaf(P.d1, l0, P.c * x1);
    float l2 = fmaf(P.d1, l1, P.c * x2);
    float l3 = fmaf(P.d1, l2, P.c * x3);
    float t = l3, u;
    u = __shfl_up_sync(FULL, t, 1);  if (lane >= 1)  t = fmaf(P.d4, u, t);
    u = __shfl_up_sync(FULL, t, 2);  if (lane >= 2)  t = fmaf(P.q1, u, t);
    u = __shfl_up_sync(FULL, t, 4);  if (lane >= 4)  t = fmaf(P.q2, u, t);
    u = __shfl_up_sync(FULL, t, 8);  if (lane >= 8)  t = fmaf(P.q3, u, t);
    u = __shfl_up_sync(FULL, t, 16); if (lane >= 16) t = fmaf(P.q4, u, t);
    float pre = __shfl_up_sync(FULL, t, 1);
    pre = (lane == 0) ? 0.0f : pre;
    s0 = fmaf(P.d1, pre, l0);
    s1 = fmaf(P.d2, pre, l1);
    s2 = fmaf(P.d3, pre, l2);
    s3 = fmaf(P.d4, pre, l3);
}

__device__ __forceinline__ void scan_bwd(const DirP& P, int lane,
        float x0, float x1, float x2, float x3,
        float& s0, float& s1, float& s2, float& s3)
{
    float r3 = P.c * x3;
    float r2 = fmaf(P.d1, r3, P.c * x2);
    float r1 = fmaf(P.d1, r2, P.c * x1);
    float r0 = fmaf(P.d1, r1, P.c * x0);
    float t = r0, u;
    u = __shfl_down_sync(FULL, t, 1);  if (lane <= 30) t = fmaf(P.d4, u, t);
    u = __shfl_down_sync(FULL, t, 2);  if (lane <= 29) t = fmaf(P.q1, u, t);
    u = __shfl_down_sync(FULL, t, 4);  if (lane <= 27) t = fmaf(P.q2, u, t);
    u = __shfl_down_sync(FULL, t, 8);  if (lane <= 23) t = fmaf(P.q3, u, t);
    u = __shfl_down_sync(FULL, t, 16); if (lane <= 15) t = fmaf(P.q4, u, t);
    float pre = __shfl_down_sync(FULL, t, 1);
    pre = (lane == 31) ? 0.0f : pre;
    s3 = fmaf(P.d1, pre, r3);
    s2 = fmaf(P.d2, pre, r2);
    s1 = fmaf(P.d3, pre, r1);
    s0 = fmaf(P.d4, pre, r0);
}

// Issue 4 cp.async.cg 16B copies per thread for one plane (swizzled).
__device__ __forceinline__ void issue_plane_load(float* buf,
                                                 const float* __restrict__ gsrc,
                                                 int tid)
{
    #pragma unroll
    for (int k = 0; k < PLANE / 4 / NT; k++) {   // 4 iterations
        const int fidx = tid + k * NT;           // 0..4095 float4s
        const int h = fidx >> 5;
        const int g = fidx & 31;
        const int pg = g ^ ((h >> 2) & 31);
        uint32_t dst = (uint32_t)__cvta_generic_to_shared(buf + h * 128 + (pg << 2));
        const float4* src = reinterpret_cast<const float4*>(gsrc) + fidx;
        asm volatile("cp.async.cg.shared.global [%0], [%1], 16;\n"
                     :: "r"(dst), "l"(src));
    }
}

__global__ __launch_bounds__(NT, 1)
void dss2d_kernel(const float* __restrict__ x,
                  const float* __restrict__ decay_logits,
                  const float* __restrict__ mix_logits,
                  const float* __restrict__ input_scale,
                  float* __restrict__ out)
{
    extern __shared__ float smem[];
    float* bufs0 = smem;                 // plane buffer 0
    float* bufs1 = smem + PLANE;         // plane buffer 1
    float* acc   = smem + 2 * PLANE;     // vertical results

    const int tid  = threadIdx.x;
    const int lane = tid & 31;
    const int wid  = tid >> 5;
    const int stride = gridDim.x;

    int p = blockIdx.x;
    if (p < NPLANES) {
        issue_plane_load(bufs0, x + (size_t)p * PLANE, tid);
    }
    asm volatile("cp.async.commit_group;\n" ::: "memory");

    int cur = 0;
    for (; p < NPLANES; p += stride) {
        asm volatile("cp.async.wait_group 0;\n" ::: "memory");
        __syncthreads();

        const int pn = p + stride;
        float* xs = cur ? bufs1 : bufs0;
        float* xn = cur ? bufs0 : bufs1;
        if (pn < NPLANES) {
            issue_plane_load(xn, x + (size_t)pn * PLANE, tid);
        }
        asm volatile("cp.async.commit_group;\n" ::: "memory");

        const int ch = p & (Cc - 1);

        // mix weights (softmax over 4 directions)
        float ml0 = mix_logits[ch];
        float ml1 = mix_logits[Cc + ch];
        float ml2 = mix_logits[2 * Cc + ch];
        float ml3 = mix_logits[3 * Cc + ch];
        float mx = fmaxf(fmaxf(ml0, ml1), fmaxf(ml2, ml3));
        float e0 = expf(ml0 - mx), e1 = expf(ml1 - mx);
        float e2 = expf(ml2 - mx), e3 = expf(ml3 - mx);
        float minv = 1.0f / (e0 + e1 + e2 + e3);
        const float m0 = e0 * minv, m1 = e1 * minv;
        const float m2 = e2 * minv, m3 = e3 * minv;

        // ---- vertical: TB + BT. Warp wid owns column group wid (4 cols);
        //      lane holds a 4x4 block; result overwrites xr in place. ----
        {
            const DirP PT = make_dir(decay_logits, input_scale, 2, ch);
            const DirP PB = make_dir(decay_logits, input_scale, 3, ch);
            const int pg = ((wid ^ lane) & 31) << 2;
            const float* base = xs + (4 * lane) * 128 + pg;
            float xr[4][4];   // [row j][col k]
            #pragma unroll
            for (int j = 0; j < 4; j++) {
                const float4 v = *reinterpret_cast<const float4*>(base + j * 128);
                xr[j][0] = v.x; xr[j][1] = v.y; xr[j][2] = v.z; xr[j][3] = v.w;
            }
            #pragma unroll
            for (int k = 0; k < 4; k++) {
                float t0, t1, t2, t3, b0, b1, b2, b3;
                scan_fwd(PT, lane, xr[0][k], xr[1][k], xr[2][k], xr[3][k],
                         t0, t1, t2, t3);
                scan_bwd(PB, lane, xr[0][k], xr[1][k], xr[2][k], xr[3][k],
                         b0, b1, b2, b3);
                xr[0][k] = fmaf(m2, t0, m3 * b0);
                xr[1][k] = fmaf(m2, t1, m3 * b1);
                xr[2][k] = fmaf(m2, t2, m3 * b2);
                xr[3][k] = fmaf(m2, t3, m3 * b3);
            }
            float* abase = acc + (4 * lane) * 128 + pg;
            #pragma unroll
            for (int j = 0; j < 4; j++) {
                *reinterpret_cast<float4*>(abase + j * 128) =
                    make_float4(xr[j][0], xr[j][1], xr[j][2], xr[j][3]);
            }
        }
        __syncthreads();

        // ---- horizontal: LR + RL, warp per row (4 rows/warp), fused STG ----
        {
            const DirP PL = make_dir(decay_logits, input_scale, 0, ch);
            const DirP PR = make_dir(decay_logits, input_scale, 1, ch);
            float4* __restrict__ dst =
                reinterpret_cast<float4*>(out + (size_t)p * PLANE);
            #pragma unroll
            for (int it = 0; it < 128 / NW; it++) {   // 4 iterations
                const int h = wid + it * NW;
                const int pg = lane ^ ((h >> 2) & 31);
                const int idx = h * 128 + (pg << 2);
                const float4 v = *reinterpret_cast<const float4*>(xs + idx);
                const float4 a = *reinterpret_cast<const float4*>(acc + idx);
                float l0, l1, l2, l3, r0, r1, r2, r3;
                scan_fwd(PL, lane, v.x, v.y, v.z, v.w, l0, l1, l2, l3);
                scan_bwd(PR, lane, v.x, v.y, v.z, v.w, r0, r1, r2, r3);
                float4 o;
                o.x = fmaf(m0, l0, fmaf(m1, r0, a.x));
                o.y = fmaf(m0, l1, fmaf(m1, r1, a.y));
                o.z = fmaf(m0, l2, fmaf(m1, r2, a.z));
                o.w = fmaf(m0, l3, fmaf(m1, r3, a.w));
                dst[h * 32 + lane] = o;
            }
        }
        __syncthreads();   // all reads of xs/acc done before next overwrite
        cur ^= 1;
    }
}

extern "C" void kernel_launch(void* const* d_in, const int* in_sizes, int n_in,
                              void* d_out, int out_size)
{
    const float* x            = (const float*)d_in[0];
    const float* decay_logits = (const float*)d_in[1];
    const float* mix_logits   = (const float*)d_in[2];
    const float* input_scale  = (const float*)d_in[3];
    float* out = (float*)d_out;

    const int smem_bytes = 3 * PLANE * sizeof(float);   // 196608
    cudaFuncSetAttribute(dss2d_kernel,
                         cudaFuncAttributeMaxDynamicSharedMemorySize,
                         smem_bytes);

    int dev = 0, nsm = 148;
    cudaGetDevice(&dev);
    cudaDeviceGetAttribute(&nsm, cudaDevAttrMultiProcessorCount, dev);
    int grid = nsm < NPLANES ? nsm : NPLANES;

    dss2d_kernel<<<grid, NT, smem_bytes>>>(
        x, decay_logits, mix_logits, input_scale, out);
}

// round 8
// speedup vs baseline: 1.0730x; 1.0730x over previous
#include <cuda_runtime.h>
#include <cstdint>

// DirectionalStateScan2D: B=8, C=256, H=128, W=128, fp32.
// Persistent CTAs, double-buffered cp.async plane prefetch, NT=512.
//
// Swizzle: phys(r,w) = r*128 + 4*((w>>2 ^ r>>2)&31) + (w&3).
// Both phases use a 4x4 register block per lane -> 8 independent shuffle
// chains per warp call (4 lines x 2 directions), hiding SHFL latency.
//  - vertical: warp owns 4 columns, lane has rows 4*lane..+3.
//  - horizontal: warp owns 4 rows, lane has cols 4*lane..+3.
// All SMEM accesses (LDS.128/STS.128) are conflict-free under the swizzle.

#define Hh 128
#define Ww 128
#define Cc 256
#define PLANE (Hh * Ww)
#define NPLANES (8 * Cc)
#define NT 512
#define NW (NT / 32)          // 16 warps
#define FULL 0xFFFFFFFFu

struct DirP {
    float d1, d2, d3, d4;   // d^1..d^4
    float q1, q2, q3, q4;   // d^8, d^16, d^32, d^64
    float c;                // (1-d)*scale
};

__device__ __forceinline__ DirP make_dir(const float* __restrict__ decay_logits,
                                         const float* __restrict__ input_scale,
                                         int dir, int ch)
{
    float d = 1.0f / (1.0f + expf(-decay_logits[dir * Cc + ch]));
    d = fminf(fmaxf(d, 0.05f), 0.995f);
    float sc = 1.0f + tanhf(input_scale[dir * Cc + ch]);
    DirP P;
    P.d1 = d;
    P.d2 = d * d;
    P.d3 = P.d2 * d;
    P.d4 = P.d2 * P.d2;
    P.q1 = P.d4 * P.d4;
    P.q2 = P.q1 * P.q1;
    P.q3 = P.q2 * P.q2;
    P.q4 = P.q3 * P.q3;
    P.c  = (1.0f - d) * sc;
    return P;
}

__device__ __forceinline__ void scan_fwd(const DirP& P, int lane,
        float x0, float x1, float x2, float x3,
        float& s0, float& s1, float& s2, float& s3)
{
    float l0 = P.c * x0;
    float l1 = fmaf(P.d1, l0, P.c * x1);
    float l2 = fmaf(P.d1, l1, P.c * x2);
    float l3 = fmaf(P.d1, l2, P.c * x3);
    float t = l3, u;
    u = __shfl_up_sync(FULL, t, 1);  if (lane >= 1)  t = fmaf(P.d4, u, t);
    u = __shfl_up_sync(FULL, t, 2);  if (lane >= 2)  t = fmaf(P.q1, u, t);
    u = __shfl_up_sync(FULL, t, 4);  if (lane >= 4)  t = fmaf(P.q2, u, t);
    u = __shfl_up_sync(FULL, t, 8);  if (lane >= 8)  t = fmaf(P.q3, u, t);
    u = __shfl_up_sync(FULL, t, 16); if (lane >= 16) t = fmaf(P.q4, u, t);
    float pre = __shfl_up_sync(FULL, t, 1);
    pre = (lane == 0) ? 0.0f : pre;
    s0 = fmaf(P.d1, pre, l0);
    s1 = fmaf(P.d2, pre, l1);
    s2 = fmaf(P.d3, pre, l2);
    s3 = fmaf(P.d4, pre, l3);
}

__device__ __forceinline__ void scan_bwd(const DirP& P, int lane,
        float x0, float x1, float x2, float x3,
        float& s0, float& s1, float& s2, float& s3)
{
    float r3 = P.c * x3;
    float r2 = fmaf(P.d1, r3, P.c * x2);
    float r1 = fmaf(P.d1, r2, P.c * x1);
    float r0 = fmaf(P.d1, r1, P.c * x0);
    float t = r0, u;
    u = __shfl_down_sync(FULL, t, 1);  if (lane <= 30) t = fmaf(P.d4, u, t);
    u = __shfl_down_sync(FULL, t, 2);  if (lane <= 29) t = fmaf(P.q1, u, t);
    u = __shfl_down_sync(FULL, t, 4);  if (lane <= 27) t = fmaf(P.q2, u, t);
    u = __shfl_down_sync(FULL, t, 8);  if (lane <= 23) t = fmaf(P.q3, u, t);
    u = __shfl_down_sync(FULL, t, 16); if (lane <= 15) t = fmaf(P.q4, u, t);
    float pre = __shfl_down_sync(FULL, t, 1);
    pre = (lane == 31) ? 0.0f : pre;
    s3 = fmaf(P.d1, pre, r3);
    s2 = fmaf(P.d2, pre, r2);
    s1 = fmaf(P.d3, pre, r1);
    s0 = fmaf(P.d4, pre, r0);
}

// Issue 8 cp.async.cg 16B copies for one plane into swizzled smem buffer.
__device__ __forceinline__ void issue_plane_load(float* buf,
                                                 const float* __restrict__ gsrc,
                                                 int tid)
{
    #pragma unroll
    for (int k = 0; k < PLANE / 4 / NT; k++) {   // 8 iterations
        const int fidx = tid + k * NT;           // 0..4095 float4s
        const int h = fidx >> 5;
        const int g = fidx & 31;
        const int pg = g ^ ((h >> 2) & 31);
        uint32_t dst = (uint32_t)__cvta_generic_to_shared(buf + h * 128 + (pg << 2));
        const float4* src = reinterpret_cast<const float4*>(gsrc) + fidx;
        asm volatile("cp.async.cg.shared.global [%0], [%1], 16;\n"
                     :: "r"(dst), "l"(src));
    }
}

__global__ __launch_bounds__(NT, 1)
void dss2d_kernel(const float* __restrict__ x,
                  const float* __restrict__ decay_logits,
                  const float* __restrict__ mix_logits,
                  const float* __restrict__ input_scale,
                  float* __restrict__ out)
{
    extern __shared__ float smem[];
    float* bufs0 = smem;                 // plane buffer 0
    float* bufs1 = smem + PLANE;         // plane buffer 1
    float* acc   = smem + 2 * PLANE;     // vertical results

    const int tid  = threadIdx.x;
    const int lane = tid & 31;
    const int wid  = tid >> 5;
    const int stride = gridDim.x;

    int p = blockIdx.x;
    if (p < NPLANES) {
        issue_plane_load(bufs0, x + (size_t)p * PLANE, tid);
    }
    asm volatile("cp.async.commit_group;\n" ::: "memory");

    int cur = 0;
    for (; p < NPLANES; p += stride) {
        asm volatile("cp.async.wait_group 0;\n" ::: "memory");
        __syncthreads();

        const int pn = p + stride;
        float* xs = cur ? bufs1 : bufs0;
        float* xn = cur ? bufs0 : bufs1;
        if (pn < NPLANES) {
            issue_plane_load(xn, x + (size_t)pn * PLANE, tid);
        }
        asm volatile("cp.async.commit_group;\n" ::: "memory");

        const int ch = p & (Cc - 1);

        // mix weights (softmax over 4 directions)
        float ml0 = mix_logits[ch];
        float ml1 = mix_logits[Cc + ch];
        float ml2 = mix_logits[2 * Cc + ch];
        float ml3 = mix_logits[3 * Cc + ch];
        float mx = fmaxf(fmaxf(ml0, ml1), fmaxf(ml2, ml3));
        float e0 = expf(ml0 - mx), e1 = expf(ml1 - mx);
        float e2 = expf(ml2 - mx), e3 = expf(ml3 - mx);
        float minv = 1.0f / (e0 + e1 + e2 + e3);
        const float m0 = e0 * minv, m1 = e1 * minv;
        const float m2 = e2 * minv, m3 = e3 * minv;

        // ---- vertical: TB + BT. Warp handles 4-column group G per iter;
        //      lane holds 4x4 block (rows 4*lane..+3, cols 4G..4G+3). ----
        {
            const DirP PT = make_dir(decay_logits, input_scale, 2, ch);
            const DirP PB = make_dir(decay_logits, input_scale, 3, ch);
            #pragma unroll
            for (int it = 0; it < 32 / NW; it++) {     // 2 macro-iters
                const int G  = wid + it * NW;          // column group 0..31
                const int pg = ((G ^ lane) & 31) << 2;
                const float* base = xs + (4 * lane) * 128 + pg;
                float xr[4][4];   // [row j][col k]
                #pragma unroll
                for (int j = 0; j < 4; j++) {
                    const float4 v = *reinterpret_cast<const float4*>(base + j * 128);
                    xr[j][0] = v.x; xr[j][1] = v.y; xr[j][2] = v.z; xr[j][3] = v.w;
                }
                #pragma unroll
                for (int k = 0; k < 4; k++) {
                    float t0, t1, t2, t3, b0, b1, b2, b3;
                    scan_fwd(PT, lane, xr[0][k], xr[1][k], xr[2][k], xr[3][k],
                             t0, t1, t2, t3);
                    scan_bwd(PB, lane, xr[0][k], xr[1][k], xr[2][k], xr[3][k],
                             b0, b1, b2, b3);
                    xr[0][k] = fmaf(m2, t0, m3 * b0);
                    xr[1][k] = fmaf(m2, t1, m3 * b1);
                    xr[2][k] = fmaf(m2, t2, m3 * b2);
                    xr[3][k] = fmaf(m2, t3, m3 * b3);
                }
                float* abase = acc + (4 * lane) * 128 + pg;
                #pragma unroll
                for (int j = 0; j < 4; j++) {
                    *reinterpret_cast<float4*>(abase + j * 128) =
                        make_float4(xr[j][0], xr[j][1], xr[j][2], xr[j][3]);
                }
            }
        }
        __syncthreads();

        // ---- horizontal: LR + RL. Warp handles 4-row block rb per iter;
        //      lane holds 4x4 block (rows 4*rb..+3, cols 4*lane..+3). ----
        {
            const DirP PL = make_dir(decay_logits, input_scale, 0, ch);
            const DirP PR = make_dir(decay_logits, input_scale, 1, ch);
            float4* __restrict__ dst =
                reinterpret_cast<float4*>(out + (size_t)p * PLANE);
            #pragma unroll
            for (int it = 0; it < 32 / NW; it++) {     // 2 macro-iters
                const int rb = wid + it * NW;          // row block 0..31
                const int R  = rb << 2;
                const int off = ((lane ^ rb) & 31) << 2;
                const float* base = xs + R * 128 + off;
                float xr[4][4];   // [row j][col k], cols 4*lane+k
                #pragma unroll
                for (int j = 0; j < 4; j++) {
                    const float4 v = *reinterpret_cast<const float4*>(base + j * 128);
                    xr[j][0] = v.x; xr[j][1] = v.y; xr[j][2] = v.z; xr[j][3] = v.w;
                }
                #pragma unroll
                for (int j = 0; j < 4; j++) {
                    float l0, l1, l2, l3, r0, r1, r2, r3;
                    scan_fwd(PL, lane, xr[j][0], xr[j][1], xr[j][2], xr[j][3],
                             l0, l1, l2, l3);
                    scan_bwd(PR, lane, xr[j][0], xr[j][1], xr[j][2], xr[j][3],
                             r0, r1, r2, r3);
                    xr[j][0] = fmaf(m0, l0, m1 * r0);
                    xr[j][1] = fmaf(m0, l1, m1 * r1);
                    xr[j][2] = fmaf(m0, l2, m1 * r2);
                    xr[j][3] = fmaf(m0, l3, m1 * r3);
                }
                const float* abase = acc + R * 128 + off;
                #pragma unroll
                for (int j = 0; j < 4; j++) {
                    const float4 a = *reinterpret_cast<const float4*>(abase + j * 128);
                    float4 o;
                    o.x = xr[j][0] + a.x;
                    o.y = xr[j][1] + a.y;
                    o.z = xr[j][2] + a.z;
                    o.w = xr[j][3] + a.w;
                    dst[(R + j) * 32 + lane] = o;
                }
            }
        }
        __syncthreads();   // all reads of xs/acc done before next overwrite
        cur ^= 1;
    }
}

extern "C" void kernel_launch(void* const* d_in, const int* in_sizes, int n_in,
                              void* d_out, int out_size)
{
    const float* x            = (const float*)d_in[0];
    const float* decay_logits = (const float*)d_in[1];
    const float* mix_logits   = (const float*)d_in[2];
    const float* input_scale  = (const float*)d_in[3];
    float* out = (float*)d_out;

    const int smem_bytes = 3 * PLANE * sizeof(float);   // 196608
    cudaFuncSetAttribute(dss2d_kernel,
                         cudaFuncAttributeMaxDynamicSharedMemorySize,
                         smem_bytes);

    int dev = 0, nsm = 148;
    cudaGetDevice(&dev);
    cudaDeviceGetAttribute(&nsm, cudaDevAttrMultiProcessorCount, dev);
    int grid = nsm < NPLANES ? nsm : NPLANES;

    dss2d_kernel<<<grid, NT, smem_bytes>>>(
        x, decay_logits, mix_logits, input_scale, out);
}

// round 9
// speedup vs baseline: 1.0794x; 1.0060x over previous
#include <cuda_runtime.h>
#include <cstdint>

// DirectionalStateScan2D: B=8, C=256, H=128, W=128, fp32.
// Persistent CTAs, double-buffered cp.async plane prefetch, NT=512.
//
// Swizzle: phys(r,w) = r*128 + 4*((w>>2 ^ r>>2)&31) + (w&3).
// Both phases use a 4x4 register block per lane -> 8 independent shuffle
// chains per warp call (4 lines x 2 directions), hiding SHFL latency.
//  - vertical: warp owns 4 columns, lane has rows 4*lane..+3.
//  - horizontal: warp owns 4 rows, lane has cols 4*lane..+3.
// All SMEM accesses (LDS.128/STS.128) are conflict-free under the swizzle.

#define Hh 128
#define Ww 128
#define Cc 256
#define PLANE (Hh * Ww)
#define NPLANES (8 * Cc)
#define NT 512
#define NW (NT / 32)          // 16 warps
#define FULL 0xFFFFFFFFu

struct DirP {
    float d1, d2, d3, d4;   // d^1..d^4
    float q1, q2, q3, q4;   // d^8, d^16, d^32, d^64
    float c;                // (1-d)*scale
};

__device__ __forceinline__ DirP make_dir(const float* __restrict__ decay_logits,
                                         const float* __restrict__ input_scale,
                                         int dir, int ch)
{
    float d = 1.0f / (1.0f + expf(-decay_logits[dir * Cc + ch]));
    d = fminf(fmaxf(d, 0.05f), 0.995f);
    float sc = 1.0f + tanhf(input_scale[dir * Cc + ch]);
    DirP P;
    P.d1 = d;
    P.d2 = d * d;
    P.d3 = P.d2 * d;
    P.d4 = P.d2 * P.d2;
    P.q1 = P.d4 * P.d4;
    P.q2 = P.q1 * P.q1;
    P.q3 = P.q2 * P.q2;
    P.q4 = P.q3 * P.q3;
    P.c  = (1.0f - d) * sc;
    return P;
}

__device__ __forceinline__ void scan_fwd(const DirP& P, int lane,
        float x0, float x1, float x2, float x3,
        float& s0, float& s1, float& s2, float& s3)
{
    float l0 = P.c * x0;
    float l1 = fmaf(P.d1, l0, P.c * x1);
    float l2 = fmaf(P.d1, l1, P.c * x2);
    float l3 = fmaf(P.d1, l2, P.c * x3);
    float t = l3, u;
    u = __shfl_up_sync(FULL, t, 1);  if (lane >= 1)  t = fmaf(P.d4, u, t);
    u = __shfl_up_sync(FULL, t, 2);  if (lane >= 2)  t = fmaf(P.q1, u, t);
    u = __shfl_up_sync(FULL, t, 4);  if (lane >= 4)  t = fmaf(P.q2, u, t);
    u = __shfl_up_sync(FULL, t, 8);  if (lane >= 8)  t = fmaf(P.q3, u, t);
    u = __shfl_up_sync(FULL, t, 16); if (lane >= 16) t = fmaf(P.q4, u, t);
    float pre = __shfl_up_sync(FULL, t, 1);
    pre = (lane == 0) ? 0.0f : pre;
    s0 = fmaf(P.d1, pre, l0);
    s1 = fmaf(P.d2, pre, l1);
    s2 = fmaf(P.d3, pre, l2);
    s3 = fmaf(P.d4, pre, l3);
}

__device__ __forceinline__ void scan_bwd(const DirP& P, int lane,
        float x0, float x1, float x2, float x3,
        float& s0, float& s1, float& s2, float& s3)
{
    float r3 = P.c * x3;
    float r2 = fmaf(P.d1, r3, P.c * x2);
    float r1 = fmaf(P.d1, r2, P.c * x1);
    float r0 = fmaf(P.d1, r1, P.c * x0);
    float t = r0, u;
    u = __shfl_down_sync(FULL, t, 1);  if (lane <= 30) t = fmaf(P.d4, u, t);
    u = __shfl_down_sync(FULL, t, 2);  if (lane <= 29) t = fmaf(P.q1, u, t);
    u = __shfl_down_sync(FULL, t, 4);  if (lane <= 27) t = fmaf(P.q2, u, t);
    u = __shfl_down_sync(FULL, t, 8);  if (lane <= 23) t = fmaf(P.q3, u, t);
    u = __shfl_down_sync(FULL, t, 16); if (lane <= 15) t = fmaf(P.q4, u, t);
    float pre = __shfl_down_sync(FULL, t, 1);
    pre = (lane == 31) ? 0.0f : pre;
    s3 = fmaf(P.d1, pre, r3);
    s2 = fmaf(P.d2, pre, r2);
    s1 = fmaf(P.d3, pre, r1);
    s0 = fmaf(P.d4, pre, r0);
}

// Issue 8 cp.async.cg 16B copies for one plane into swizzled smem buffer.
__device__ __forceinline__ void issue_plane_load(float* buf,
                                                 const float* __restrict__ gsrc,
                                                 int tid)
{
    #pragma unroll
    for (int k = 0; k < PLANE / 4 / NT; k++) {   // 8 iterations
        const int fidx = tid + k * NT;           // 0..4095 float4s
        const int h = fidx >> 5;
        const int g = fidx & 31;
        const int pg = g ^ ((h >> 2) & 31);
        uint32_t dst = (uint32_t)__cvta_generic_to_shared(buf + h * 128 + (pg << 2));
        const float4* src = reinterpret_cast<const float4*>(gsrc) + fidx;
        asm volatile("cp.async.cg.shared.global [%0], [%1], 16;\n"
                     :: "r"(dst), "l"(src));
    }
}

__global__ __launch_bounds__(NT, 1)
void dss2d_kernel(const float* __restrict__ x,
                  const float* __restrict__ decay_logits,
                  const float* __restrict__ mix_logits,
                  const float* __restrict__ input_scale,
                  float* __restrict__ out)
{
    extern __shared__ float smem[];
    float* bufs0 = smem;                 // plane buffer 0
    float* bufs1 = smem + PLANE;         // plane buffer 1
    float* acc   = smem + 2 * PLANE;     // vertical results

    const int tid  = threadIdx.x;
    const int lane = tid & 31;
    const int wid  = tid >> 5;
    const int stride = gridDim.x;

    int p = blockIdx.x;
    if (p < NPLANES) {
        issue_plane_load(bufs0, x + (size_t)p * PLANE, tid);
    }
    asm volatile("cp.async.commit_group;\n" ::: "memory");

    int cur = 0;
    for (; p < NPLANES; p += stride) {
        asm volatile("cp.async.wait_group 0;\n" ::: "memory");
        __syncthreads();

        const int pn = p + stride;
        float* xs = cur ? bufs1 : bufs0;
        float* xn = cur ? bufs0 : bufs1;
        if (pn < NPLANES) {
            issue_plane_load(xn, x + (size_t)pn * PLANE, tid);
        }
        asm volatile("cp.async.commit_group;\n" ::: "memory");

        const int ch = p & (Cc - 1);

        // mix weights (softmax over 4 directions)
        float ml0 = mix_logits[ch];
        float ml1 = mix_logits[Cc + ch];
        float ml2 = mix_logits[2 * Cc + ch];
        float ml3 = mix_logits[3 * Cc + ch];
        float mx = fmaxf(fmaxf(ml0, ml1), fmaxf(ml2, ml3));
        float e0 = expf(ml0 - mx), e1 = expf(ml1 - mx);
        float e2 = expf(ml2 - mx), e3 = expf(ml3 - mx);
        float minv = 1.0f / (e0 + e1 + e2 + e3);
        const float m0 = e0 * minv, m1 = e1 * minv;
        const float m2 = e2 * minv, m3 = e3 * minv;

        // ---- vertical: TB + BT. Warp handles 4-column group G per iter;
        //      lane holds 4x4 block (rows 4*lane..+3, cols 4G..4G+3). ----
        {
            const DirP PT = make_dir(decay_logits, input_scale, 2, ch);
            const DirP PB = make_dir(decay_logits, input_scale, 3, ch);
            #pragma unroll
            for (int it = 0; it < 32 / NW; it++) {     // 2 macro-iters
                const int G  = wid + it * NW;          // column group 0..31
                const int pg = ((G ^ lane) & 31) << 2;
                const float* base = xs + (4 * lane) * 128 + pg;
                float xr[4][4];   // [row j][col k]
                #pragma unroll
                for (int j = 0; j < 4; j++) {
                    const float4 v = *reinterpret_cast<const float4*>(base + j * 128);
                    xr[j][0] = v.x; xr[j][1] = v.y; xr[j][2] = v.z; xr[j][3] = v.w;
                }
                #pragma unroll
                for (int k = 0; k < 4; k++) {
                    float t0, t1, t2, t3, b0, b1, b2, b3;
                    scan_fwd(PT, lane, xr[0][k], xr[1][k], xr[2][k], xr[3][k],
                             t0, t1, t2, t3);
                    scan_bwd(PB, lane, xr[0][k], xr[1][k], xr[2][k], xr[3][k],
                             b0, b1, b2, b3);
                    xr[0][k] = fmaf(m2, t0, m3 * b0);
                    xr[1][k] = fmaf(m2, t1, m3 * b1);
                    xr[2][k] = fmaf(m2, t2, m3 * b2);
                    xr[3][k] = fmaf(m2, t3, m3 * b3);
                }
                float* abase = acc + (4 * lane) * 128 + pg;
                #pragma unroll
                for (int j = 0; j < 4; j++) {
                    *reinterpret_cast<float4*>(abase + j * 128) =
                        make_float4(xr[j][0], xr[j][1], xr[j][2], xr[j][3]);
                }
            }
        }
        __syncthreads();

        // ---- horizontal: LR + RL. Warp handles 4-row block rb per iter;
        //      lane holds 4x4 block (rows 4*rb..+3, cols 4*lane..+3). ----
        {
            const DirP PL = make_dir(decay_logits, input_scale, 0, ch);
            const DirP PR = make_dir(decay_logits, input_scale, 1, ch);
            float4* __restrict__ dst =
                reinterpret_cast<float4*>(out + (size_t)p * PLANE);
            #pragma unroll
            for (int it = 0; it < 32 / NW; it++) {     // 2 macro-iters
                const int rb = wid + it * NW;          // row block 0..31
                const int R  = rb << 2;
                const int off = ((lane ^ rb) & 31) << 2;
                const float* base = xs + R * 128 + off;
                float xr[4][4];   // [row j][col k], cols 4*lane+k
                #pragma unroll
                for (int j = 0; j < 4; j++) {
                    const float4 v = *reinterpret_cast<const float4*>(base + j * 128);
                    xr[j][0] = v.x; xr[j][1] = v.y; xr[j][2] = v.z; xr[j][3] = v.w;
                }
                #pragma unroll
                for (int j = 0; j < 4; j++) {
                    float l0, l1, l2, l3, r0, r1, r2, r3;
                    scan_fwd(PL, lane, xr[j][0], xr[j][1], xr[j][2], xr[j][3],
                             l0, l1, l2, l3);
                    scan_bwd(PR, lane, xr[j][0], xr[j][1], xr[j][2], xr[j][3],
                             r0, r1, r2, r3);
                    xr[j][0] = fmaf(m0, l0, m1 * r0);
                    xr[j][1] = fmaf(m0, l1, m1 * r1);
                    xr[j][2] = fmaf(m0, l2, m1 * r2);
                    xr[j][3] = fmaf(m0, l3, m1 * r3);
                }
                const float* abase = acc + R * 128 + off;
                #pragma unroll
                for (int j = 0; j < 4; j++) {
                    const float4 a = *reinterpret_cast<const float4*>(abase + j * 128);
                    float4 o;
                    o.x = xr[j][0] + a.x;
                    o.y = xr[j][1] + a.y;
                    o.z = xr[j][2] + a.z;
                    o.w = xr[j][3] + a.w;
                    dst[(R + j) * 32 + lane] = o;
                }
            }
        }
        __syncthreads();   // all reads of xs/acc done before next overwrite
        cur ^= 1;
    }
}

extern "C" void kernel_launch(void* const* d_in, const int* in_sizes, int n_in,
                              void* d_out, int out_size)
{
    const float* x            = (const float*)d_in[0];
    const float* decay_logits = (const float*)d_in[1];
    const float* mix_logits   = (const float*)d_in[2];
    const float* input_scale  = (const float*)d_in[3];
    float* out = (float*)d_out;

    const int smem_bytes = 3 * PLANE * sizeof(float);   // 196608
    cudaFuncSetAttribute(dss2d_kernel,
                         cudaFuncAttributeMaxDynamicSharedMemorySize,
                         smem_bytes);

    int dev = 0, nsm = 148;
    cudaGetDevice(&dev);
    cudaDeviceGetAttribute(&nsm, cudaDevAttrMultiProcessorCount, dev);
    int grid = nsm < NPLANES ? nsm : NPLANES;

    dss2d_kernel<<<grid, NT, smem_bytes>>>(
        x, decay_logits, mix_logits, input_scale, out);
}